// round 14
// baseline (speedup 1.0000x reference)
#include <cuda_runtime.h>
#include <math.h>

// SpectralCirculantLayer: y = ifft(fft(x) * H) + bias, N=4096 per row, B=8192.
// rfft-4096 via c2c-2048 (even/odd pack), spectral multiply on bins 0..1023 (H
// truncated), one-sided inverse pack, irfft via c2c-2048.
// Radix 16*16*8 Stockham (3 smem stages per direction), separate midstage,
// STS.128 stage-1 writes (stride-18 padding), dual-chain twiddles (R13 wins).
// THIS ROUND: TWO-ROW INTERLEAVE. 128 threads/CTA, each CTA processes rows
// A and B concurrently (4 smem buffers, 80KB/CTA, 2 CTAs/SM -> 255-reg
// budget). Same 4 rows in flight per SM, but barriers halve (6 per 2 rows)
// and every inter-barrier region carries two independent dependency chains
// (row B's compute hides row A's LDS/LDG latency in-thread).

#define NTHREADS 128
#define SB16 2304   // 2048 + 2*(2048/16) padding (stride-18 rows, 16B aligned)

__device__ __forceinline__ int pd(int i) { return i + ((i >> 4) << 1); }

__device__ __forceinline__ float2 cadd(float2 a, float2 b) { return make_float2(a.x + b.x, a.y + b.y); }
__device__ __forceinline__ float2 csub(float2 a, float2 b) { return make_float2(a.x - b.x, a.y - b.y); }
__device__ __forceinline__ float2 cmul(float2 a, float2 b) {
    return make_float2(fmaf(a.x, b.x, -a.y * b.y), fmaf(a.x, b.y, a.y * b.x));
}
__device__ __forceinline__ float2 conjf2(float2 a) { return make_float2(a.x, -a.y); }

template <int DIR>
__device__ __forceinline__ float2 mulJ(float2 a) {
    return (DIR < 0) ? make_float2(a.y, -a.x) : make_float2(-a.y, a.x);
}

template <int DIR>
__device__ __forceinline__ void dft4(float2* v) {
    float2 s0 = cadd(v[0], v[2]), d0 = csub(v[0], v[2]);
    float2 s1 = cadd(v[1], v[3]), d1 = mulJ<DIR>(csub(v[1], v[3]));
    v[0] = cadd(s0, s1);
    v[1] = cadd(d0, d1);
    v[2] = csub(s0, s1);
    v[3] = csub(d0, d1);
}

template <int DIR>
__device__ __forceinline__ void dft8(float2* v) {
    const float HC = 0.70710678118654752f;
    float2 b0 = cadd(v[0], v[4]);
    float2 b1 = cadd(v[1], v[5]);
    float2 b2 = cadd(v[2], v[6]);
    float2 b3 = cadd(v[3], v[7]);
    float2 c0 = csub(v[0], v[4]);
    float2 c1 = cmul(csub(v[1], v[5]), make_float2(HC, DIR * HC));
    float2 c2 = mulJ<DIR>(csub(v[2], v[6]));
    float2 c3 = cmul(csub(v[3], v[7]), make_float2(-HC, DIR * HC));
    {
        float2 s0 = cadd(b0, b2), d0 = csub(b0, b2);
        float2 s1 = cadd(b1, b3), d1 = mulJ<DIR>(csub(b1, b3));
        v[0] = cadd(s0, s1);
        v[2] = cadd(d0, d1);
        v[4] = csub(s0, s1);
        v[6] = csub(d0, d1);
    }
    {
        float2 s0 = cadd(c0, c2), d0 = csub(c0, c2);
        float2 s1 = cadd(c1, c3), d1 = mulJ<DIR>(csub(c1, c3));
        v[1] = cadd(s0, s1);
        v[3] = cadd(d0, d1);
        v[5] = csub(s0, s1);
        v[7] = csub(d0, d1);
    }
}

// 16-point DFT in registers: two radix-4 levels (Stockham, self-sorting).
template <int DIR>
__device__ __forceinline__ void dft16(float2* v) {
    const float C1 = 0.92387953251128675f;
    const float S1 = 0.38268343236508977f;
    const float H2 = 0.70710678118654752f;
    const float2 W1 = make_float2(C1, DIR * S1);
    const float2 W2 = make_float2(H2, DIR * H2);
    const float2 W3 = make_float2(S1, DIR * C1);
    const float2 W6 = make_float2(-H2, DIR * H2);
    const float2 W9 = make_float2(-C1, -DIR * S1);

    float2 u[16];
#pragma unroll
    for (int i = 0; i < 4; i++) {
        float2 a[4] = {v[i], v[i + 4], v[i + 8], v[i + 12]};
        dft4<DIR>(a);
        u[4 * i + 0] = a[0];
        u[4 * i + 1] = a[1];
        u[4 * i + 2] = a[2];
        u[4 * i + 3] = a[3];
    }
    {
        float2 a[4] = {u[0], u[4], u[8], u[12]};
        dft4<DIR>(a);
        v[0] = a[0]; v[4] = a[1]; v[8] = a[2]; v[12] = a[3];
    }
    {
        float2 a[4] = {u[1], cmul(u[5], W1), cmul(u[9], W2), cmul(u[13], W3)};
        dft4<DIR>(a);
        v[1] = a[0]; v[5] = a[1]; v[9] = a[2]; v[13] = a[3];
    }
    {
        float2 a[4] = {u[2], cmul(u[6], W2), mulJ<DIR>(u[10]), cmul(u[14], W6)};
        dft4<DIR>(a);
        v[2] = a[0]; v[6] = a[1]; v[10] = a[2]; v[14] = a[3];
    }
    {
        float2 a[4] = {u[3], cmul(u[7], W3), cmul(u[11], W6), cmul(u[15], W9)};
        dft4<DIR>(a);
        v[3] = a[0]; v[7] = a[1]; v[11] = a[2]; v[15] = a[3];
    }
}

// Stage 1: radix-16, NS=1. Reads global (GIN) or padded smem.
// Output pd(16*tl+r) = 18*tl+r contiguous -> STS.128.
template <int DIR, bool GIN>
__device__ __forceinline__ void stage_r16_ns1(const float2* __restrict__ in,
                                              float2* __restrict__ out, int tl) {
    float2 v[16];
#pragma unroll
    for (int r = 0; r < 16; r++) v[r] = GIN ? in[tl + (r << 7)] : in[pd(tl + (r << 7))];
    dft16<DIR>(v);
    float4* __restrict__ o4 = reinterpret_cast<float4*>(out) + 9 * tl;  // (18*tl)/2
#pragma unroll
    for (int q = 0; q < 8; q++)
        o4[q] = make_float4(v[2 * q].x, v[2 * q].y, v[2 * q + 1].x, v[2 * q + 1].y);
}

// Stage 2: radix-16, NS=16. Dual-chain twiddle powers.
template <int DIR>
__device__ __forceinline__ void stage_r16_ns16(const float2* __restrict__ in,
                                               float2* __restrict__ out, int tl, float2 wb) {
    float2 v[16];
#pragma unroll
    for (int r = 0; r < 16; r++) v[r] = in[pd(tl + (r << 7))];
    {
        float2 p2 = cmul(wb, wb);
        float2 wo = wb;
        float2 we = p2;
        v[1] = cmul(v[1], wo);
        v[2] = cmul(v[2], we);
#pragma unroll
        for (int r = 3; r < 16; r += 2) {
            wo = cmul(wo, p2);
            v[r] = cmul(v[r], wo);
            if (r + 1 < 16) {
                we = cmul(we, p2);
                v[r + 1] = cmul(v[r + 1], we);
            }
        }
    }
    dft16<DIR>(v);
    const int jm = tl & 15, jd = tl >> 4;
    const int o = (jd << 8) + jm;
#pragma unroll
    for (int r = 0; r < 16; r++) out[pd(o + (r << 4))] = v[r];
}

// Stage 3: radix-8, NS=256. Two butterflies per thread. Dual-chain twiddles.
// GOUT: write to global with bias add (coalesced).
template <int DIR, bool GOUT>
__device__ __forceinline__ void stage_r8_ns256(const float2* __restrict__ in,
                                               float2* __restrict__ out, int tl,
                                               float2 wA, float2 wB, float bv) {
#pragma unroll
    for (int h = 0; h < 2; h++) {
        const int j = tl + (h << 7);
        const float2 wb = h ? wB : wA;
        float2 v[8];
#pragma unroll
        for (int r = 0; r < 8; r++) v[r] = in[pd(j + (r << 8))];
        {
            float2 p2 = cmul(wb, wb);
            float2 wo = wb;
            float2 we = p2;
            v[1] = cmul(v[1], wo);
            v[2] = cmul(v[2], we);
            wo = cmul(wo, p2); v[3] = cmul(v[3], wo);
            we = cmul(we, p2); v[4] = cmul(v[4], we);
            wo = cmul(wo, p2); v[5] = cmul(v[5], wo);
            we = cmul(we, p2); v[6] = cmul(v[6], we);
            wo = cmul(wo, p2); v[7] = cmul(v[7], wo);
        }
        dft8<DIR>(v);
#pragma unroll
        for (int r = 0; r < 8; r++) {
            if (GOUT)
                out[j + (r << 8)] = make_float2(v[r].x + bv, v[r].y + bv);
            else
                out[pd(j + (r << 8))] = v[r];
        }
    }
}

// Untangle rfft, multiply by H, repack one-sided for inverse.
__device__ __forceinline__ void midstage(const float2* __restrict__ S, float2* __restrict__ D,
                                         const float2* __restrict__ Hs, int tl, float2 wqb) {
    const float MCC[8] = {1.0f, 0.98078528040323044f, 0.92387953251128675f, 0.83146961230254524f,
                          0.70710678118654752f, 0.55557023301960222f, 0.38268343236508977f, 0.19509032201612827f};
    const float MCS[8] = {0.0f, -0.19509032201612827f, -0.38268343236508977f, -0.55557023301960222f,
                          -0.70710678118654752f, -0.83146961230254524f, -0.92387953251128675f, -0.98078528040323044f};
#pragma unroll
    for (int i = 0; i < 8; i++) {
        const int k = tl + (i << 7);
        const float2 wq = cmul(wqb, make_float2(MCC[i], MCS[i]));  // e^{-2pi*i*k/4096}
        float2 Zk = S[pd(k)];
        float2 Zm = S[pd((2048 - k) & 2047)];
        float2 E = make_float2(0.5f * (Zk.x + Zm.x), 0.5f * (Zk.y - Zm.y));
        float2 O = make_float2(0.5f * (Zk.y + Zm.y), -0.5f * (Zk.x - Zm.x));
        float2 Xk = cadd(E, cmul(O, wq));
        float2 Hk = Hs[k];
        float2 Yk = cmul(Xk, Hk);
        const float sc = 1.0f / 4096.0f;
        Yk.x *= sc;
        Yk.y *= sc;
        const float cph = wq.x, sph = -wq.y;
        D[pd(k)] = cmul(Yk, make_float2(1.0f - sph, cph));
        if (k > 0) {
            float2 Yc = make_float2(Yk.x, -Yk.y);
            D[pd(2048 - k)] = cmul(Yc, make_float2(1.0f + sph, cph));
        } else {
            D[pd(1024)] = make_float2(0.0f, 0.0f);
        }
    }
}

__global__ void __launch_bounds__(NTHREADS, 2)
spectral_circulant_kernel(const float* __restrict__ x, const float* __restrict__ wre,
                          const float* __restrict__ wim, const float* __restrict__ bias,
                          float* __restrict__ out, int nrows) {
    extern __shared__ float2 sm[];
    float2* XA = sm;
    float2* YA = sm + SB16;
    float2* XB = sm + 2 * SB16;
    float2* YB = sm + 3 * SB16;
    float2* Hs = sm + 4 * SB16;  // 1024 float2
    const int tl = threadIdx.x;  // 0..127

    for (int k = tl; k < 1024; k += NTHREADS) Hs[k] = make_float2(__ldg(wre + k), __ldg(wim + k));
    const float bv = __ldg(bias);

    // Per-thread row-invariant twiddle bases
    float s, c;
    sincospif(-(float)(tl & 15) * (1.0f / 128.0f), &s, &c);
    const float2 w2f = make_float2(c, s);  // e^{-2pi*i*(tl&15)/256}
    sincospif(-(float)tl * (1.0f / 1024.0f), &s, &c);
    const float2 w3f = make_float2(c, s);  // e^{-2pi*i*tl/2048}
    sincospif(-(float)tl * (1.0f / 2048.0f), &s, &c);
    const float2 wqb = make_float2(c, s);  // e^{-2pi*i*tl/4096}
    const float2 E8 = make_float2(0.92387953251128675f, -0.38268343236508977f);  // e^{-i*pi/8}
    const float2 w3g = cmul(w3f, E8);
    const float2 w2i = conjf2(w2f);
    const float2 w3i = conjf2(w3f);
    const float2 w3gi = conjf2(w3g);
    __syncthreads();  // Hs visible

    // nrows is even and base is even -> rows base, base+1 both valid.
    for (int base = blockIdx.x * 2; base < nrows; base += gridDim.x * 2) {
        const float2* xinA = reinterpret_cast<const float2*>(x) + (size_t)base * 2048;
        const float2* xinB = xinA + 2048;
        float2* youtA = reinterpret_cast<float2*>(out) + (size_t)base * 2048;
        float2* youtB = youtA + 2048;

        // Forward stage 1 (global -> smem), both rows
        stage_r16_ns1<-1, true>(xinA, YA, tl);
        stage_r16_ns1<-1, true>(xinB, YB, tl);
        __syncthreads();
        // Forward stage 2
        stage_r16_ns16<-1>(YA, XA, tl, w2f);
        stage_r16_ns16<-1>(YB, XB, tl, w2f);
        __syncthreads();
        // Forward stage 3
        stage_r8_ns256<-1, false>(XA, YA, tl, w3f, w3g, 0.0f);
        stage_r8_ns256<-1, false>(XB, YB, tl, w3f, w3g, 0.0f);
        __syncthreads();
        // Mid
        midstage(YA, XA, Hs, tl, wqb);
        midstage(YB, XB, Hs, tl, wqb);
        __syncthreads();
        // Inverse stage 1
        stage_r16_ns1<1, false>(XA, YA, tl);
        stage_r16_ns1<1, false>(XB, YB, tl);
        __syncthreads();
        // Inverse stage 2
        stage_r16_ns16<1>(YA, XA, tl, w2i);
        stage_r16_ns16<1>(YB, XB, tl, w2i);
        __syncthreads();
        // Inverse stage 3 (smem -> global with bias)
        stage_r8_ns256<1, true>(XA, youtA, tl, w3i, w3gi, bv);
        stage_r8_ns256<1, true>(XB, youtB, tl, w3i, w3gi, bv);
        // no trailing barrier: these X reads precede the barrier after the
        // next iteration's stage 1 (which writes Y); X is next written only
        // after a later barrier.
    }
}

extern "C" void kernel_launch(void* const* d_in, const int* in_sizes, int n_in,
                              void* d_out, int out_size) {
    const float* x = (const float*)d_in[0];
    const float* wre = (const float*)d_in[1];
    const float* wim = (const float*)d_in[2];
    const float* bias = (const float*)d_in[3];
    float* out = (float*)d_out;

    const int nrows = in_sizes[0] / 4096;  // 8192 (even)
    const int smem_bytes = (4 * SB16 + 1024) * sizeof(float2);  // 81920

    static int grid = 0;
    if (grid == 0) {
        cudaFuncSetAttribute(spectral_circulant_kernel,
                             cudaFuncAttributeMaxDynamicSharedMemorySize, smem_bytes);
        int nsm = 148;
        cudaDeviceGetAttribute(&nsm, cudaDevAttrMultiProcessorCount, 0);
        grid = 2 * nsm;  // persistent, 2 CTAs/SM (2 rows each)
    }

    spectral_circulant_kernel<<<grid, NTHREADS, smem_bytes>>>(x, wre, wim, bias, out, nrows);
}

// round 15
// speedup vs baseline: 1.3088x; 1.3088x over previous
#include <cuda_runtime.h>
#include <math.h>

// SpectralCirculantLayer: y = ifft(fft(x) * H) + bias, N=4096 per row, B=8192.
// rfft-4096 via c2c-2048 (even/odd pack), spectral multiply on bins 0..1023 (H
// truncated), one-sided inverse pack, irfft via c2c-2048.
// Radix 16*16*8 Stockham, 128 threads/CTA, ONE row per CTA, 4 CTAs/SM,
// stride-18 padding, STS.128 stage-1 writes, dual-chain twiddles (R13 base,
// 89.5us). THIS ROUND: midstage writes its output in the contiguous layout
// inverse stage 1 consumes (bin t+128r at slot 18t+r): midstage 16 STS.64 ->
// 8 STS.128, inv-s1 16 LDS.64 -> 8 LDS.128. All patterns conflict-free per
// 8-lane phase; zero liveness delta beyond the buffered mirror values.

#define NTHREADS 128
#define SB16 2304   // 2048 + 2*(2048/16) padding (stride-18 rows, 16B aligned)

__device__ __forceinline__ int pd(int i) { return i + ((i >> 4) << 1); }

__device__ __forceinline__ float2 cadd(float2 a, float2 b) { return make_float2(a.x + b.x, a.y + b.y); }
__device__ __forceinline__ float2 csub(float2 a, float2 b) { return make_float2(a.x - b.x, a.y - b.y); }
__device__ __forceinline__ float2 cmul(float2 a, float2 b) {
    return make_float2(fmaf(a.x, b.x, -a.y * b.y), fmaf(a.x, b.y, a.y * b.x));
}
__device__ __forceinline__ float2 conjf2(float2 a) { return make_float2(a.x, -a.y); }
__device__ __forceinline__ float4 pack2(float2 a, float2 b) { return make_float4(a.x, a.y, b.x, b.y); }

template <int DIR>
__device__ __forceinline__ float2 mulJ(float2 a) {
    return (DIR < 0) ? make_float2(a.y, -a.x) : make_float2(-a.y, a.x);
}

template <int DIR>
__device__ __forceinline__ void dft4(float2* v) {
    float2 s0 = cadd(v[0], v[2]), d0 = csub(v[0], v[2]);
    float2 s1 = cadd(v[1], v[3]), d1 = mulJ<DIR>(csub(v[1], v[3]));
    v[0] = cadd(s0, s1);
    v[1] = cadd(d0, d1);
    v[2] = csub(s0, s1);
    v[3] = csub(d0, d1);
}

template <int DIR>
__device__ __forceinline__ void dft8(float2* v) {
    const float HC = 0.70710678118654752f;
    float2 b0 = cadd(v[0], v[4]);
    float2 b1 = cadd(v[1], v[5]);
    float2 b2 = cadd(v[2], v[6]);
    float2 b3 = cadd(v[3], v[7]);
    float2 c0 = csub(v[0], v[4]);
    float2 c1 = cmul(csub(v[1], v[5]), make_float2(HC, DIR * HC));
    float2 c2 = mulJ<DIR>(csub(v[2], v[6]));
    float2 c3 = cmul(csub(v[3], v[7]), make_float2(-HC, DIR * HC));
    {
        float2 s0 = cadd(b0, b2), d0 = csub(b0, b2);
        float2 s1 = cadd(b1, b3), d1 = mulJ<DIR>(csub(b1, b3));
        v[0] = cadd(s0, s1);
        v[2] = cadd(d0, d1);
        v[4] = csub(s0, s1);
        v[6] = csub(d0, d1);
    }
    {
        float2 s0 = cadd(c0, c2), d0 = csub(c0, c2);
        float2 s1 = cadd(c1, c3), d1 = mulJ<DIR>(csub(c1, c3));
        v[1] = cadd(s0, s1);
        v[3] = cadd(d0, d1);
        v[5] = csub(s0, s1);
        v[7] = csub(d0, d1);
    }
}

// 16-point DFT in registers: two radix-4 levels (Stockham, self-sorting).
template <int DIR>
__device__ __forceinline__ void dft16(float2* v) {
    const float C1 = 0.92387953251128675f;
    const float S1 = 0.38268343236508977f;
    const float H2 = 0.70710678118654752f;
    const float2 W1 = make_float2(C1, DIR * S1);
    const float2 W2 = make_float2(H2, DIR * H2);
    const float2 W3 = make_float2(S1, DIR * C1);
    const float2 W6 = make_float2(-H2, DIR * H2);
    const float2 W9 = make_float2(-C1, -DIR * S1);

    float2 u[16];
#pragma unroll
    for (int i = 0; i < 4; i++) {
        float2 a[4] = {v[i], v[i + 4], v[i + 8], v[i + 12]};
        dft4<DIR>(a);
        u[4 * i + 0] = a[0];
        u[4 * i + 1] = a[1];
        u[4 * i + 2] = a[2];
        u[4 * i + 3] = a[3];
    }
    {
        float2 a[4] = {u[0], u[4], u[8], u[12]};
        dft4<DIR>(a);
        v[0] = a[0]; v[4] = a[1]; v[8] = a[2]; v[12] = a[3];
    }
    {
        float2 a[4] = {u[1], cmul(u[5], W1), cmul(u[9], W2), cmul(u[13], W3)};
        dft4<DIR>(a);
        v[1] = a[0]; v[5] = a[1]; v[9] = a[2]; v[13] = a[3];
    }
    {
        float2 a[4] = {u[2], cmul(u[6], W2), mulJ<DIR>(u[10]), cmul(u[14], W6)};
        dft4<DIR>(a);
        v[2] = a[0]; v[6] = a[1]; v[10] = a[2]; v[14] = a[3];
    }
    {
        float2 a[4] = {u[3], cmul(u[7], W3), cmul(u[11], W6), cmul(u[15], W9)};
        dft4<DIR>(a);
        v[3] = a[0]; v[7] = a[1]; v[11] = a[2]; v[15] = a[3];
    }
}

// Fwd stage 1: radix-16, NS=1, reads global. Output 18*tl+r contiguous -> STS.128.
__device__ __forceinline__ void stage_f1(const float2* __restrict__ in,
                                         float2* __restrict__ out, int tl) {
    float2 v[16];
#pragma unroll
    for (int r = 0; r < 16; r++) v[r] = in[tl + (r << 7)];
    dft16<-1>(v);
    float4* __restrict__ o4 = reinterpret_cast<float4*>(out) + 9 * tl;
#pragma unroll
    for (int q = 0; q < 8; q++) o4[q] = pack2(v[2 * q], v[2 * q + 1]);
}

// Inv stage 1: radix-16, NS=1, reads CONTIGUOUS layout (slot 18*tl+r holds
// D[tl+128r]) via LDS.128; writes 18*tl+r contiguous via STS.128.
__device__ __forceinline__ void stage_i1(const float2* __restrict__ in,
                                         float2* __restrict__ out, int tl) {
    float2 v[16];
    const float4* __restrict__ i4 = reinterpret_cast<const float4*>(in) + 9 * tl;
#pragma unroll
    for (int q = 0; q < 8; q++) {
        float4 f = i4[q];
        v[2 * q] = make_float2(f.x, f.y);
        v[2 * q + 1] = make_float2(f.z, f.w);
    }
    dft16<1>(v);
    float4* __restrict__ o4 = reinterpret_cast<float4*>(out) + 9 * tl;
#pragma unroll
    for (int q = 0; q < 8; q++) o4[q] = pack2(v[2 * q], v[2 * q + 1]);
}

// Stage 2: radix-16, NS=16. Dual-chain twiddle powers.
template <int DIR>
__device__ __forceinline__ void stage_r16_ns16(const float2* __restrict__ in,
                                               float2* __restrict__ out, int tl, float2 wb) {
    float2 v[16];
#pragma unroll
    for (int r = 0; r < 16; r++) v[r] = in[pd(tl + (r << 7))];
    {
        float2 p2 = cmul(wb, wb);
        float2 wo = wb;
        float2 we = p2;
        v[1] = cmul(v[1], wo);
        v[2] = cmul(v[2], we);
#pragma unroll
        for (int r = 3; r < 16; r += 2) {
            wo = cmul(wo, p2);
            v[r] = cmul(v[r], wo);
            if (r + 1 < 16) {
                we = cmul(we, p2);
                v[r + 1] = cmul(v[r + 1], we);
            }
        }
    }
    dft16<DIR>(v);
    const int jm = tl & 15, jd = tl >> 4;
    const int o = (jd << 8) + jm;
#pragma unroll
    for (int r = 0; r < 16; r++) out[pd(o + (r << 4))] = v[r];
}

// Stage 3: radix-8, NS=256. Two butterflies per thread. Dual-chain twiddles.
// GOUT: write to global with bias add (coalesced).
template <int DIR, bool GOUT>
__device__ __forceinline__ void stage_r8_ns256(const float2* __restrict__ in,
                                               float2* __restrict__ out, int tl,
                                               float2 wA, float2 wB, float bv) {
#pragma unroll
    for (int h = 0; h < 2; h++) {
        const int j = tl + (h << 7);
        const float2 wb = h ? wB : wA;
        float2 v[8];
#pragma unroll
        for (int r = 0; r < 8; r++) v[r] = in[pd(j + (r << 8))];
        {
            float2 p2 = cmul(wb, wb);
            float2 wo = wb;
            float2 we = p2;
            v[1] = cmul(v[1], wo);
            v[2] = cmul(v[2], we);
            wo = cmul(wo, p2); v[3] = cmul(v[3], wo);
            we = cmul(we, p2); v[4] = cmul(v[4], we);
            wo = cmul(wo, p2); v[5] = cmul(v[5], wo);
            we = cmul(we, p2); v[6] = cmul(v[6], we);
            wo = cmul(wo, p2); v[7] = cmul(v[7], wo);
        }
        dft8<DIR>(v);
#pragma unroll
        for (int r = 0; r < 8; r++) {
            if (GOUT)
                out[j + (r << 8)] = make_float2(v[r].x + bv, v[r].y + bv);
            else
                out[pd(j + (r << 8))] = v[r];
        }
    }
}

// Untangle rfft, multiply by H, repack one-sided for inverse.
// Writes the CONTIGUOUS inv-s1 layout: bin t+128r -> slot 18t+r.
// Main bins (k = tl+128i, i=0..7) -> addrs 18*tl + i      (4 STS.128)
// Mirror bins (2048-k)            -> addrs 18*(128-tl)+8+p (4 STS.128)
//   tl>0: p = 7-i;  tl==0: row 0 addrs 8..15: slot8 = bin1024 = 0, slot 16-i = mirror(i).
__device__ __forceinline__ void midstage(const float2* __restrict__ S, float2* __restrict__ Dc,
                                         const float2* __restrict__ Hs, int tl, float2 wqb) {
    const float MCC[8] = {1.0f, 0.98078528040323044f, 0.92387953251128675f, 0.83146961230254524f,
                          0.70710678118654752f, 0.55557023301960222f, 0.38268343236508977f, 0.19509032201612827f};
    const float MCS[8] = {0.0f, -0.19509032201612827f, -0.38268343236508977f, -0.55557023301960222f,
                          -0.70710678118654752f, -0.83146961230254524f, -0.92387953251128675f, -0.98078528040323044f};
    float2 mainv[8], mirv[8];
#pragma unroll
    for (int i = 0; i < 8; i++) {
        const int k = tl + (i << 7);
        const float2 wq = cmul(wqb, make_float2(MCC[i], MCS[i]));  // e^{-2pi*i*k/4096}
        float2 Zk = S[pd(k)];
        float2 Zm = S[pd((2048 - k) & 2047)];
        float2 E = make_float2(0.5f * (Zk.x + Zm.x), 0.5f * (Zk.y - Zm.y));
        float2 O = make_float2(0.5f * (Zk.y + Zm.y), -0.5f * (Zk.x - Zm.x));
        float2 Xk = cadd(E, cmul(O, wq));
        float2 Yk = cmul(Xk, Hs[k]);
        const float sc = 1.0f / 4096.0f;
        Yk.x *= sc;
        Yk.y *= sc;
        const float cph = wq.x, sph = -wq.y;
        mainv[i] = cmul(Yk, make_float2(1.0f - sph, cph));
        mirv[i] = cmul(conjf2(Yk), make_float2(1.0f + sph, cph));
    }
    // Main block: slots 18*tl + 0..7
    float4* __restrict__ m4 = reinterpret_cast<float4*>(Dc) + 9 * tl;
#pragma unroll
    for (int q = 0; q < 4; q++) m4[q] = pack2(mainv[2 * q], mainv[2 * q + 1]);
    // Mirror block
    if (tl > 0) {
        // slots 18*(128-tl) + 8..15, position p = 7-i
        float4* __restrict__ r4 = reinterpret_cast<float4*>(Dc) + 9 * (128 - tl) + 4;
#pragma unroll
        for (int q = 0; q < 4; q++) r4[q] = pack2(mirv[7 - 2 * q], mirv[6 - 2 * q]);
    } else {
        // row 0 slots 8..15: slot 8 = bin 1024 = 0; slot 16-i = mirv[i], i = 1..7
        float2 w[8];
        w[0] = make_float2(0.0f, 0.0f);
#pragma unroll
        for (int i = 1; i < 8; i++) w[8 - i] = mirv[i];
        float4* __restrict__ r4 = reinterpret_cast<float4*>(Dc) + 4;
#pragma unroll
        for (int q = 0; q < 4; q++) r4[q] = pack2(w[2 * q], w[2 * q + 1]);
    }
}

__global__ void __launch_bounds__(NTHREADS, 4)
spectral_circulant_kernel(const float* __restrict__ x, const float* __restrict__ wre,
                          const float* __restrict__ wim, const float* __restrict__ bias,
                          float* __restrict__ out, int nrows) {
    extern __shared__ float2 sm[];
    float2* X = sm;
    float2* Y = sm + SB16;
    float2* Hs = sm + 2 * SB16;  // 1024 float2
    const int tl = threadIdx.x;  // 0..127

    for (int k = tl; k < 1024; k += NTHREADS) Hs[k] = make_float2(__ldg(wre + k), __ldg(wim + k));
    const float bv = __ldg(bias);

    // Per-thread twiddle bases (row-invariant)
    float s, c;
    sincospif(-(float)(tl & 15) * (1.0f / 128.0f), &s, &c);
    const float2 w2f = make_float2(c, s);  // e^{-2pi*i*(tl&15)/256}
    sincospif(-(float)tl * (1.0f / 1024.0f), &s, &c);
    const float2 w3f = make_float2(c, s);  // e^{-2pi*i*tl/2048}
    sincospif(-(float)tl * (1.0f / 2048.0f), &s, &c);
    const float2 wqb = make_float2(c, s);  // e^{-2pi*i*tl/4096}
    const float2 E8 = make_float2(0.92387953251128675f, -0.38268343236508977f);  // e^{-i*pi/8}
    const float2 w3g = cmul(w3f, E8);
    const float2 w2i = conjf2(w2f);
    const float2 w3i = conjf2(w3f);
    const float2 w3gi = conjf2(w3g);
    __syncthreads();  // Hs visible

    for (int row = blockIdx.x; row < nrows; row += gridDim.x) {
        const float2* xin = reinterpret_cast<const float2*>(x) + (size_t)row * 2048;
        float2* yout = reinterpret_cast<float2*>(out) + (size_t)row * 2048;

        // Forward c2c-2048: G -> Y -> X -> Y
        stage_f1(xin, Y, tl);
        __syncthreads();
        stage_r16_ns16<-1>(Y, X, tl, w2f);
        __syncthreads();
        stage_r8_ns256<-1, false>(X, Y, tl, w3f, w3g, 0.0f);
        __syncthreads();

        // Mid: Y -> X (contiguous inv-s1 layout)
        midstage(Y, X, Hs, tl, wqb);
        __syncthreads();

        // Inverse c2c-2048: X -> Y -> X -> G
        stage_i1(X, Y, tl);
        __syncthreads();
        stage_r16_ns16<1>(Y, X, tl, w2i);
        __syncthreads();
        stage_r8_ns256<1, true>(X, yout, tl, w3i, w3gi, bv);
        // no trailing barrier: this stage's X reads precede the barrier after
        // the next row's stage 1 (which writes Y); X is next written only
        // after a later barrier.
    }
}

extern "C" void kernel_launch(void* const* d_in, const int* in_sizes, int n_in,
                              void* d_out, int out_size) {
    const float* x = (const float*)d_in[0];
    const float* wre = (const float*)d_in[1];
    const float* wim = (const float*)d_in[2];
    const float* bias = (const float*)d_in[3];
    float* out = (float*)d_out;

    const int nrows = in_sizes[0] / 4096;  // 8192
    const int smem_bytes = (2 * SB16 + 1024) * sizeof(float2);  // 45056

    static int grid = 0;
    if (grid == 0) {
        cudaFuncSetAttribute(spectral_circulant_kernel,
                             cudaFuncAttributeMaxDynamicSharedMemorySize, smem_bytes);
        int nsm = 148;
        cudaDeviceGetAttribute(&nsm, cudaDevAttrMultiProcessorCount, 0);
        grid = 4 * nsm;  // persistent, 4 CTAs/SM (1 row each)
    }

    spectral_circulant_kernel<<<grid, NTHREADS, smem_bytes>>>(x, wre, wim, bias, out, nrows);
}